// round 1
// baseline (speedup 1.0000x reference)
#include <cuda_runtime.h>
#include <math.h>

#define SPLIT 8
#define SCP 1040   // score smem pitch (supports kv_len up to 8192+)

// ---------------- scratch (no allocations allowed) ----------------
__device__ float g_xT[4096 * 16];                     // x transposed [k][b]
__device__ float g_qkv[6144 * 16];                    // q(0..4095)/k(4096..5119)/v(5120..6143) rows x 16 batches
__device__ float g_attnT[4096 * 16];                  // attention out transposed [k][b]
__device__ float g_part_o[16 * 8 * 4 * SPLIT * 128];  // split-KV partial outputs
__device__ float g_part_ml[16 * 8 * 4 * SPLIT * 2];   // split-KV partial (m, l)

// ---------------- helpers ----------------
__device__ __forceinline__ unsigned long long ffma2(unsigned long long a, unsigned long long b, unsigned long long c) {
    unsigned long long d;
    asm("fma.rn.f32x2 %0, %1, %2, %3;" : "=l"(d) : "l"(a), "l"(b), "l"(c));
    return d;
}
__device__ __forceinline__ unsigned long long addf2(unsigned long long a, unsigned long long b) {
    unsigned long long d;
    asm("add.rn.f32x2 %0, %1, %2;" : "=l"(d) : "l"(a), "l"(b));
    return d;
}
__device__ __forceinline__ unsigned long long pack2(float v) {
    unsigned long long d;
    asm("mov.b64 %0, {%1, %1};" : "=l"(d) : "r"(__float_as_uint(v)));
    return d;
}
__device__ __forceinline__ float f2lo(unsigned long long u) { return __uint_as_float((unsigned)u); }
__device__ __forceinline__ float f2hi(unsigned long long u) { return __uint_as_float((unsigned)(u >> 32)); }
__device__ __forceinline__ float ex2f_fast(float x) {
    float y;
    asm("ex2.approx.ftz.f32 %0, %1;" : "=f"(y) : "f"(x));
    return y;
}

// ---------------- kernel 1: transpose x [16][4096] -> xT [4096][16] ----------------
__global__ void transpose_x_kernel(const float* __restrict__ x) {
    int i = blockIdx.x * 256 + threadIdx.x;   // i = k*16 + b
    g_xT[i] = x[(i & 15) * 4096 + (i >> 4)];
}

// ---------------- kernel 2/5: 16-batch GEMV with f32x2 packed FMA ----------------
// mode 0: QKV projection (W selected per row region), RoPE + softmax-scale fused, out -> g_qkv[row*16+b]
// mode 1: out projection (W = Wa = wo), x from g_attnT, out -> outp[b*4096 + row]
__global__ __launch_bounds__(256) void gemv16_kernel(
    const float* __restrict__ Wa, const float* __restrict__ Wb, const float* __restrict__ Wc,
    float* __restrict__ outp,
    const float* __restrict__ fc, const float* __restrict__ fs, int mode)
{
    __shared__ __align__(16) float xs[512 * 20];  // 512 k-rows x 16 batches, pitch 20 floats (bank-conflict-free)
    const int tid = threadIdx.x, lane = tid & 31, wid = tid >> 5;
    const int r0 = blockIdx.x * 32 + wid * 4;

    const float* W;
    const float* xT;
    int row;
    if (mode == 0) {
        xT = g_xT;
        if (r0 < 4096)      { W = Wa; row = r0; }
        else if (r0 < 5120) { W = Wb; row = r0 - 4096; }
        else                { W = Wc; row = r0 - 5120; }
    } else {
        xT = g_attnT; W = Wa; row = r0;
    }
    float* op = (mode == 0) ? g_qkv : outp;

    unsigned long long acc[4][8];
#pragma unroll
    for (int r = 0; r < 4; r++)
#pragma unroll
        for (int p = 0; p < 8; p++) acc[r][p] = 0ull;

    const float4* xT4 = (const float4*)xT;
    for (int kb = 0; kb < 8; kb++) {
        // cooperative load of 512x16 chunk into padded smem
#pragma unroll
        for (int i = tid; i < 2048; i += 256) {
            int kl = i >> 2, q = i & 3;
            float4 v = xT4[(kb * 512 + kl) * 4 + q];
            *(float4*)&xs[kl * 20 + q * 4] = v;
        }
        __syncthreads();

        const float* wr = W + (size_t)row * 4096 + kb * 512;
#pragma unroll 4
        for (int it = 0; it < 16; it++) {
            int k = it * 32 + lane;
            unsigned long long p0 = pack2(wr[k]);
            unsigned long long p1 = pack2(wr[4096 + k]);
            unsigned long long p2 = pack2(wr[2 * 4096 + k]);
            unsigned long long p3 = pack2(wr[3 * 4096 + k]);
            const ulonglong2* xp = (const ulonglong2*)&xs[k * 20];
#pragma unroll
            for (int pp = 0; pp < 4; pp++) {
                ulonglong2 xv = xp[pp];
                acc[0][2 * pp]     = ffma2(p0, xv.x, acc[0][2 * pp]);
                acc[0][2 * pp + 1] = ffma2(p0, xv.y, acc[0][2 * pp + 1]);
                acc[1][2 * pp]     = ffma2(p1, xv.x, acc[1][2 * pp]);
                acc[1][2 * pp + 1] = ffma2(p1, xv.y, acc[1][2 * pp + 1]);
                acc[2][2 * pp]     = ffma2(p2, xv.x, acc[2][2 * pp]);
                acc[2][2 * pp + 1] = ffma2(p2, xv.y, acc[2][2 * pp + 1]);
                acc[3][2 * pp]     = ffma2(p3, xv.x, acc[3][2 * pp]);
                acc[3][2 * pp + 1] = ffma2(p3, xv.y, acc[3][2 * pp + 1]);
            }
        }
        __syncthreads();
    }

    // reduce k-partials across lanes (all lanes end with full sums)
#pragma unroll
    for (int r = 0; r < 4; r++)
#pragma unroll
        for (int p = 0; p < 8; p++) {
#pragma unroll
            for (int off = 16; off > 0; off >>= 1) {
                unsigned long long o = __shfl_xor_sync(0xffffffffu, acc[r][p], off);
                acc[r][p] = addf2(acc[r][p], o);
            }
        }

    if (lane < 16) {
        const int b = lane;
        float v[4];
#pragma unroll
        for (int r = 0; r < 4; r++) {
            unsigned long long u = acc[r][b >> 1];
            v[r] = (b & 1) ? f2hi(u) : f2lo(u);
        }
        if (mode == 0) {
            if (r0 < 5120) {  // RoPE for q and k rows
                int i0 = (r0 & 127) >> 1;
                float c0 = fc[i0], s0 = fs[i0], c1 = fc[i0 + 1], s1 = fs[i0 + 1];
                float a0 = v[0] * c0 - v[1] * s0, b0 = v[0] * s0 + v[1] * c0;
                float a1 = v[2] * c1 - v[3] * s1, b1 = v[2] * s1 + v[3] * c1;
                v[0] = a0; v[1] = b0; v[2] = a1; v[3] = b1;
                if (r0 < 4096) {  // fold softmax scale * log2(e) into q
                    const float SC = 1.4426950408889634f * 0.08838834764831843f;
                    v[0] *= SC; v[1] *= SC; v[2] *= SC; v[3] *= SC;
                }
            }
#pragma unroll
            for (int r = 0; r < 4; r++) op[(r0 + r) * 16 + b] = v[r];
        } else {
#pragma unroll
            for (int r = 0; r < 4; r++) op[b * 4096 + r0 + r] = v[r];
        }
    }
}

// ---------------- kernel 3: split-KV flash-decode partials ----------------
__global__ __launch_bounds__(256) void attn_partial_kernel(
    const float* __restrict__ cache_k, const float* __restrict__ cache_v,
    const int* __restrict__ sp_ptr)
{
    __shared__ __align__(16) float q_s[512];
    __shared__ __align__(16) float sc[4 * SCP];
    __shared__ __align__(16) float o_red[8 * 512];
    __shared__ float m_s[4], l_s[4];
    __shared__ float red_s[8][4];

    const int tid = threadIdx.x, lane = tid & 31, wid = tid >> 5;
    const int blk = blockIdx.x;
    const int chunk = blk & (SPLIT - 1);
    const int kvh = (blk >> 3) & 7;
    const int b = blk >> 6;
    const int sp = *sp_ptr;
    const int kvlen = sp + 1;
    const int CH = (kvlen + SPLIT - 1) / SPLIT;
    const int c0 = chunk * CH;
    const int c1 = min(c0 + CH, kvlen);
    const int len = c1 - c0;

    // load the 4 q heads sharing this kv head (already scaled by scale*log2e)
    for (int i = tid; i < 512; i += 256)
        q_s[i] = g_qkv[((kvh * 4 + (i >> 7)) * 128 + (i & 127)) * 16 + b];
    __syncthreads();

    float qr[4][4];
#pragma unroll
    for (int h = 0; h < 4; h++) {
        float4 t = *(const float4*)&q_s[h * 128 + lane * 4];
        qr[h][0] = t.x; qr[h][1] = t.y; qr[h][2] = t.z; qr[h][3] = t.w;
    }

    // ---- Phase A: scores ----
    for (int j = c0 + wid; j < c1; j += 8) {
        float4 kv;
        if (j < sp) {
            kv = *(const float4*)(cache_k + (((size_t)b * 8192 + j) * 8 + kvh) * 128 + lane * 4);
        } else {
            int base = (4096 + kvh * 128 + lane * 4) * 16 + b;
            kv.x = g_qkv[base]; kv.y = g_qkv[base + 16]; kv.z = g_qkv[base + 32]; kv.w = g_qkv[base + 48];
        }
        float s0 = kv.x * qr[0][0] + kv.y * qr[0][1] + kv.z * qr[0][2] + kv.w * qr[0][3];
        float s1 = kv.x * qr[1][0] + kv.y * qr[1][1] + kv.z * qr[1][2] + kv.w * qr[1][3];
        float s2 = kv.x * qr[2][0] + kv.y * qr[2][1] + kv.z * qr[2][2] + kv.w * qr[2][3];
        float s3 = kv.x * qr[3][0] + kv.y * qr[3][1] + kv.z * qr[3][2] + kv.w * qr[3][3];
#pragma unroll
        for (int off = 16; off > 0; off >>= 1) {
            s0 += __shfl_xor_sync(0xffffffffu, s0, off);
            s1 += __shfl_xor_sync(0xffffffffu, s1, off);
            s2 += __shfl_xor_sync(0xffffffffu, s2, off);
            s3 += __shfl_xor_sync(0xffffffffu, s3, off);
        }
        if (lane == 0) {
            int jj = j - c0;
            sc[jj] = s0; sc[SCP + jj] = s1; sc[2 * SCP + jj] = s2; sc[3 * SCP + jj] = s3;
        }
    }
    __syncthreads();

    // ---- chunk max per head ----
    float lm[4] = {-1e30f, -1e30f, -1e30f, -1e30f};
    for (int i = tid; i < len; i += 256) {
#pragma unroll
        for (int h = 0; h < 4; h++) lm[h] = fmaxf(lm[h], sc[h * SCP + i]);
    }
#pragma unroll
    for (int off = 16; off > 0; off >>= 1) {
#pragma unroll
        for (int h = 0; h < 4; h++)
            lm[h] = fmaxf(lm[h], __shfl_xor_sync(0xffffffffu, lm[h], off));
    }
    if (lane == 0) {
#pragma unroll
        for (int h = 0; h < 4; h++) red_s[wid][h] = lm[h];
    }
    __syncthreads();
    if (tid < 4) {
        float m = red_s[0][tid];
#pragma unroll
        for (int w = 1; w < 8; w++) m = fmaxf(m, red_s[w][tid]);
        m_s[tid] = m;
    }
    __syncthreads();

    // ---- exp2 pass + row sums ----
    float lp[4] = {0.f, 0.f, 0.f, 0.f};
    const float m0 = m_s[0], m1 = m_s[1], m2 = m_s[2], m3 = m_s[3];
    for (int i = tid; i < len; i += 256) {
        float p0 = ex2f_fast(sc[i] - m0);           sc[i] = p0;            lp[0] += p0;
        float p1 = ex2f_fast(sc[SCP + i] - m1);     sc[SCP + i] = p1;      lp[1] += p1;
        float p2 = ex2f_fast(sc[2 * SCP + i] - m2); sc[2 * SCP + i] = p2;  lp[2] += p2;
        float p3 = ex2f_fast(sc[3 * SCP + i] - m3); sc[3 * SCP + i] = p3;  lp[3] += p3;
    }
#pragma unroll
    for (int off = 16; off > 0; off >>= 1) {
#pragma unroll
        for (int h = 0; h < 4; h++)
            lp[h] += __shfl_xor_sync(0xffffffffu, lp[h], off);
    }
    if (lane == 0) {
#pragma unroll
        for (int h = 0; h < 4; h++) red_s[wid][h] = lp[h];
    }
    __syncthreads();
    if (tid < 4) {
        float l = 0.f;
#pragma unroll
        for (int w = 0; w < 8; w++) l += red_s[w][tid];
        l_s[tid] = l;
    }

    // ---- Phase B: weighted V accumulation ----
    float4 o0 = {0,0,0,0}, o1 = {0,0,0,0}, o2 = {0,0,0,0}, o3 = {0,0,0,0};
    for (int j = c0 + wid; j < c1; j += 8) {
        float4 vv;
        if (j < sp) {
            vv = *(const float4*)(cache_v + (((size_t)b * 8192 + j) * 8 + kvh) * 128 + lane * 4);
        } else {
            int base = (5120 + kvh * 128 + lane * 4) * 16 + b;
            vv.x = g_qkv[base]; vv.y = g_qkv[base + 16]; vv.z = g_qkv[base + 32]; vv.w = g_qkv[base + 48];
        }
        int jj = j - c0;
        float p0 = sc[jj], p1 = sc[SCP + jj], p2 = sc[2 * SCP + jj], p3 = sc[3 * SCP + jj];
        o0.x += p0 * vv.x; o0.y += p0 * vv.y; o0.z += p0 * vv.z; o0.w += p0 * vv.w;
        o1.x += p1 * vv.x; o1.y += p1 * vv.y; o1.z += p1 * vv.z; o1.w += p1 * vv.w;
        o2.x += p2 * vv.x; o2.y += p2 * vv.y; o2.z += p2 * vv.z; o2.w += p2 * vv.w;
        o3.x += p3 * vv.x; o3.y += p3 * vv.y; o3.z += p3 * vv.z; o3.w += p3 * vv.w;
    }

    // ---- cross-warp reduce + write partials ----
    *(float4*)&o_red[wid * 512 + 0 * 128 + lane * 4] = o0;
    *(float4*)&o_red[wid * 512 + 1 * 128 + lane * 4] = o1;
    *(float4*)&o_red[wid * 512 + 2 * 128 + lane * 4] = o2;
    *(float4*)&o_red[wid * 512 + 3 * 128 + lane * 4] = o3;
    __syncthreads();

    for (int e = tid; e < 512; e += 256) {
        float s = 0.f;
#pragma unroll
        for (int w = 0; w < 8; w++) s += o_red[w * 512 + e];
        int h = e >> 7, d = e & 127;
        g_part_o[(((b * 8 + kvh) * 4 + h) * SPLIT + chunk) * 128 + d] = s;
    }
    if (tid < 4) {
        int pidx = ((b * 8 + kvh) * 4 + tid) * SPLIT + chunk;
        g_part_ml[pidx * 2]     = m_s[tid];
        g_part_ml[pidx * 2 + 1] = l_s[tid];
    }
}

// ---------------- kernel 4: split-KV softmax combine -> attnT ----------------
__global__ void attn_combine_kernel() {
    const int qh = blockIdx.x & 31;
    const int b = blockIdx.x >> 5;
    const int kvh = qh >> 2, h = qh & 3;
    const int pidx = ((b * 8 + kvh) * 4 + h) * SPLIT;
    const int d = threadIdx.x;

    float mg[SPLIT], lg[SPLIT];
    float M = -1e30f;
#pragma unroll
    for (int g = 0; g < SPLIT; g++) {
        mg[g] = g_part_ml[(pidx + g) * 2];
        lg[g] = g_part_ml[(pidx + g) * 2 + 1];
        M = fmaxf(M, mg[g]);
    }
    float L = 0.f, wg[SPLIT];
#pragma unroll
    for (int g = 0; g < SPLIT; g++) {
        wg[g] = ex2f_fast(mg[g] - M);
        L += lg[g] * wg[g];
    }
    float s = 0.f;
#pragma unroll
    for (int g = 0; g < SPLIT; g++)
        s += g_part_o[(pidx + g) * 128 + d] * wg[g];

    g_attnT[(qh * 128 + d) * 16 + b] = s / L;
}

// ---------------- launch ----------------
extern "C" void kernel_launch(void* const* d_in, const int* in_sizes, int n_in,
                              void* d_out, int out_size) {
    const float* x  = (const float*)d_in[0];
    const int*   sp = (const int*)d_in[1];
    const float* fc = (const float*)d_in[2];
    const float* fs = (const float*)d_in[3];
    const float* ck = (const float*)d_in[4];
    const float* cv = (const float*)d_in[5];
    const float* wq = (const float*)d_in[6];
    const float* wk = (const float*)d_in[7];
    const float* wv = (const float*)d_in[8];
    const float* wo = (const float*)d_in[9];
    float* out = (float*)d_out;

    transpose_x_kernel<<<256, 256>>>(x);
    gemv16_kernel<<<192, 256>>>(wq, wk, wv, nullptr, fc, fs, 0);
    attn_partial_kernel<<<16 * 8 * SPLIT, 256>>>(ck, cv, sp);
    attn_combine_kernel<<<512, 128>>>();
    gemv16_kernel<<<128, 256>>>(wo, nullptr, nullptr, out, nullptr, nullptr, 1);
}

// round 2
// speedup vs baseline: 1.3180x; 1.3180x over previous
#include <cuda_runtime.h>
#include <math.h>

#define SPLIT 8
#define SCP 516          // score smem pitch (CH = ceil(4097/8) = 513)
#define ATN_THREADS 192  // 6 warps
#define ATN_WARPS 6

// ---------------- scratch (no allocations allowed) ----------------
__device__ float g_xT[4096 * 16];                     // x transposed [k][b]
__device__ float g_qkv[6144 * 16];                    // q(0..4095)/k(4096..5119)/v(5120..6143) rows x 16 batches
__device__ float g_attnT[4096 * 16];                  // attention out transposed [k][b]
__device__ float g_part_o[16 * 8 * 4 * SPLIT * 128];  // split-KV partial outputs
__device__ float g_part_ml[16 * 8 * 4 * SPLIT * 2];   // split-KV partial (m, l)

// ---------------- helpers ----------------
__device__ __forceinline__ unsigned long long ffma2(unsigned long long a, unsigned long long b, unsigned long long c) {
    unsigned long long d;
    asm("fma.rn.f32x2 %0, %1, %2, %3;" : "=l"(d) : "l"(a), "l"(b), "l"(c));
    return d;
}
__device__ __forceinline__ unsigned long long addf2(unsigned long long a, unsigned long long b) {
    unsigned long long d;
    asm("add.rn.f32x2 %0, %1, %2;" : "=l"(d) : "l"(a), "l"(b));
    return d;
}
__device__ __forceinline__ unsigned long long pack2(float v) {
    unsigned long long d;
    asm("mov.b64 %0, {%1, %1};" : "=l"(d) : "r"(__float_as_uint(v)));
    return d;
}
__device__ __forceinline__ float f2lo(unsigned long long u) { return __uint_as_float((unsigned)u); }
__device__ __forceinline__ float f2hi(unsigned long long u) { return __uint_as_float((unsigned)(u >> 32)); }
__device__ __forceinline__ float ex2f_fast(float x) {
    float y;
    asm("ex2.approx.ftz.f32 %0, %1;" : "=f"(y) : "f"(x));
    return y;
}

// ---------------- kernel 1: transpose x [16][4096] -> xT [4096][16] ----------------
__global__ void transpose_x_kernel(const float* __restrict__ x) {
    int i = blockIdx.x * 256 + threadIdx.x;   // i = k*16 + b
    g_xT[i] = x[(i & 15) * 4096 + (i >> 4)];
}

// ---------------- kernel 2/5: 16-batch GEMV, 2 rows/warp, f32x2 packed FMA ----------------
// mode 0: QKV projection (W per row region), RoPE + softmax-scale fused, out -> g_qkv[row*16+b]
// mode 1: out projection (W = Wa = wo), x from g_attnT, out -> outp[b*4096 + row]
__global__ __launch_bounds__(256) void gemv16_kernel(
    const float* __restrict__ Wa, const float* __restrict__ Wb, const float* __restrict__ Wc,
    float* __restrict__ outp,
    const float* __restrict__ fc, const float* __restrict__ fs, int mode)
{
    __shared__ __align__(16) float xs[512 * 20];  // 512 k-rows x 16 batches, pitch 20 (conflict-free)
    const int tid = threadIdx.x, lane = tid & 31, wid = tid >> 5;
    const int r0 = blockIdx.x * 16 + wid * 2;

    const float* W;
    const float* xT;
    int row;
    if (mode == 0) {
        xT = g_xT;
        if (r0 < 4096)      { W = Wa; row = r0; }
        else if (r0 < 5120) { W = Wb; row = r0 - 4096; }
        else                { W = Wc; row = r0 - 5120; }
    } else {
        xT = g_attnT; W = Wa; row = r0;
    }
    float* op = (mode == 0) ? g_qkv : outp;

    unsigned long long acc[2][8];
#pragma unroll
    for (int r = 0; r < 2; r++)
#pragma unroll
        for (int p = 0; p < 8; p++) acc[r][p] = 0ull;

    const float4* xT4 = (const float4*)xT;
    for (int kb = 0; kb < 8; kb++) {
#pragma unroll
        for (int i = tid; i < 2048; i += 256) {
            int kl = i >> 2, q = i & 3;
            float4 v = xT4[(kb * 512 + kl) * 4 + q];
            *(float4*)&xs[kl * 20 + q * 4] = v;
        }
        __syncthreads();

        const float* wr = W + (size_t)row * 4096 + kb * 512;
#pragma unroll 8
        for (int it = 0; it < 16; it++) {
            int k = it * 32 + lane;
            unsigned long long p0 = pack2(wr[k]);
            unsigned long long p1 = pack2(wr[4096 + k]);
            const ulonglong2* xp = (const ulonglong2*)&xs[k * 20];
#pragma unroll
            for (int pp = 0; pp < 4; pp++) {
                ulonglong2 xv = xp[pp];
                acc[0][2 * pp]     = ffma2(p0, xv.x, acc[0][2 * pp]);
                acc[0][2 * pp + 1] = ffma2(p0, xv.y, acc[0][2 * pp + 1]);
                acc[1][2 * pp]     = ffma2(p1, xv.x, acc[1][2 * pp]);
                acc[1][2 * pp + 1] = ffma2(p1, xv.y, acc[1][2 * pp + 1]);
            }
        }
        __syncthreads();
    }

    // reduce k-partials across lanes
#pragma unroll
    for (int r = 0; r < 2; r++)
#pragma unroll
        for (int p = 0; p < 8; p++) {
#pragma unroll
            for (int off = 16; off > 0; off >>= 1) {
                unsigned long long o = __shfl_xor_sync(0xffffffffu, acc[r][p], off);
                acc[r][p] = addf2(acc[r][p], o);
            }
        }

    if (lane < 16) {
        const int b = lane;
        float v[2];
#pragma unroll
        for (int r = 0; r < 2; r++) {
            unsigned long long u = acc[r][b >> 1];
            v[r] = (b & 1) ? f2hi(u) : f2lo(u);
        }
        if (mode == 0) {
            if (r0 < 5120) {  // RoPE for q and k rows (r0 even -> rows are a rope pair)
                int i0 = (r0 & 127) >> 1;
                float c0 = fc[i0], s0 = fs[i0];
                float a0 = v[0] * c0 - v[1] * s0, b0 = v[0] * s0 + v[1] * c0;
                v[0] = a0; v[1] = b0;
                if (r0 < 4096) {  // fold softmax scale * log2(e) into q
                    const float SC = 1.4426950408889634f * 0.08838834764831843f;
                    v[0] *= SC; v[1] *= SC;
                }
            }
            op[r0 * 16 + b] = v[0];
            op[(r0 + 1) * 16 + b] = v[1];
        } else {
            op[b * 4096 + r0] = v[0];
            op[b * 4096 + r0 + 1] = v[1];
        }
    }
}

// shfl butterfly for 4 values
__device__ __forceinline__ void red4(float& s0, float& s1, float& s2, float& s3) {
#pragma unroll
    for (int off = 16; off > 0; off >>= 1) {
        s0 += __shfl_xor_sync(0xffffffffu, s0, off);
        s1 += __shfl_xor_sync(0xffffffffu, s1, off);
        s2 += __shfl_xor_sync(0xffffffffu, s2, off);
        s3 += __shfl_xor_sync(0xffffffffu, s3, off);
    }
}

// ---------------- kernel 3: split-KV flash-decode partials ----------------
__global__ __launch_bounds__(ATN_THREADS, 7) void attn_partial_kernel(
    const float* __restrict__ cache_k, const float* __restrict__ cache_v,
    const int* __restrict__ sp_ptr)
{
    __shared__ __align__(16) float q_s[512];
    __shared__ __align__(16) float sc[4 * SCP];
    __shared__ __align__(16) float o_red[ATN_WARPS * 512];
    __shared__ float m_s[4], l_s[4];
    __shared__ float red_s[ATN_WARPS][4];

    const int tid = threadIdx.x, lane = tid & 31, wid = tid >> 5;
    const int blk = blockIdx.x;
    const int chunk = blk & (SPLIT - 1);
    const int kvh = (blk >> 3) & 7;
    const int b = blk >> 6;
    const int sp = *sp_ptr;
    const int kvlen = sp + 1;
    const int CH = (kvlen + SPLIT - 1) / SPLIT;
    const int c0 = chunk * CH;
    const int c1 = min(c0 + CH, kvlen);
    const int len = c1 - c0;
    const bool has_new = (sp >= c0 && sp < c1);
    const int jmax = min(c1, sp);   // cache-resident keys only

    // load the 4 q heads sharing this kv head (pre-scaled by scale*log2e)
    for (int i = tid; i < 512; i += ATN_THREADS)
        q_s[i] = g_qkv[((kvh * 4 + (i >> 7)) * 128 + (i & 127)) * 16 + b];
    __syncthreads();

    float qr[4][4];
#pragma unroll
    for (int h = 0; h < 4; h++) {
        float4 t = *(const float4*)&q_s[h * 128 + lane * 4];
        qr[h][0] = t.x; qr[h][1] = t.y; qr[h][2] = t.z; qr[h][3] = t.w;
    }

    const float* kbase = cache_k + (size_t)b * 8192 * 1024 + kvh * 128 + lane * 4;

    // ---- Phase A: scores (unroll 2, batched loads) ----
    {
        int j = c0 + wid;
        for (; j + ATN_WARPS < jmax; j += 2 * ATN_WARPS) {
            float4 k0 = *(const float4*)(kbase + (size_t)j * 1024);
            float4 k1 = *(const float4*)(kbase + (size_t)(j + ATN_WARPS) * 1024);
            float s0 = k0.x*qr[0][0] + k0.y*qr[0][1] + k0.z*qr[0][2] + k0.w*qr[0][3];
            float s1 = k0.x*qr[1][0] + k0.y*qr[1][1] + k0.z*qr[1][2] + k0.w*qr[1][3];
            float s2 = k0.x*qr[2][0] + k0.y*qr[2][1] + k0.z*qr[2][2] + k0.w*qr[2][3];
            float s3 = k0.x*qr[3][0] + k0.y*qr[3][1] + k0.z*qr[3][2] + k0.w*qr[3][3];
            float t0 = k1.x*qr[0][0] + k1.y*qr[0][1] + k1.z*qr[0][2] + k1.w*qr[0][3];
            float t1 = k1.x*qr[1][0] + k1.y*qr[1][1] + k1.z*qr[1][2] + k1.w*qr[1][3];
            float t2 = k1.x*qr[2][0] + k1.y*qr[2][1] + k1.z*qr[2][2] + k1.w*qr[2][3];
            float t3 = k1.x*qr[3][0] + k1.y*qr[3][1] + k1.z*qr[3][2] + k1.w*qr[3][3];
            red4(s0, s1, s2, s3);
            red4(t0, t1, t2, t3);
            if (lane == 0) {
                int jj = j - c0;
                sc[jj] = s0; sc[SCP + jj] = s1; sc[2*SCP + jj] = s2; sc[3*SCP + jj] = s3;
                jj += ATN_WARPS;
                sc[jj] = t0; sc[SCP + jj] = t1; sc[2*SCP + jj] = t2; sc[3*SCP + jj] = t3;
            }
        }
        for (; j < jmax; j += ATN_WARPS) {
            float4 k0 = *(const float4*)(kbase + (size_t)j * 1024);
            float s0 = k0.x*qr[0][0] + k0.y*qr[0][1] + k0.z*qr[0][2] + k0.w*qr[0][3];
            float s1 = k0.x*qr[1][0] + k0.y*qr[1][1] + k0.z*qr[1][2] + k0.w*qr[1][3];
            float s2 = k0.x*qr[2][0] + k0.y*qr[2][1] + k0.z*qr[2][2] + k0.w*qr[2][3];
            float s3 = k0.x*qr[3][0] + k0.y*qr[3][1] + k0.z*qr[3][2] + k0.w*qr[3][3];
            red4(s0, s1, s2, s3);
            if (lane == 0) {
                int jj = j - c0;
                sc[jj] = s0; sc[SCP + jj] = s1; sc[2*SCP + jj] = s2; sc[3*SCP + jj] = s3;
            }
        }
        // new token (from g_qkv)
        if (has_new && wid == 0) {
            int base = (4096 + kvh * 128 + lane * 4) * 16 + b;
            float4 kv;
            kv.x = g_qkv[base]; kv.y = g_qkv[base + 16]; kv.z = g_qkv[base + 32]; kv.w = g_qkv[base + 48];
            float s0 = kv.x*qr[0][0] + kv.y*qr[0][1] + kv.z*qr[0][2] + kv.w*qr[0][3];
            float s1 = kv.x*qr[1][0] + kv.y*qr[1][1] + kv.z*qr[1][2] + kv.w*qr[1][3];
            float s2 = kv.x*qr[2][0] + kv.y*qr[2][1] + kv.z*qr[2][2] + kv.w*qr[2][3];
            float s3 = kv.x*qr[3][0] + kv.y*qr[3][1] + kv.z*qr[3][2] + kv.w*qr[3][3];
            red4(s0, s1, s2, s3);
            if (lane == 0) {
                int jj = sp - c0;
                sc[jj] = s0; sc[SCP + jj] = s1; sc[2*SCP + jj] = s2; sc[3*SCP + jj] = s3;
            }
        }
    }
    __syncthreads();

    // ---- chunk max per head ----
    float lm[4] = {-1e30f, -1e30f, -1e30f, -1e30f};
    for (int i = tid; i < len; i += ATN_THREADS) {
#pragma unroll
        for (int h = 0; h < 4; h++) lm[h] = fmaxf(lm[h], sc[h * SCP + i]);
    }
#pragma unroll
    for (int off = 16; off > 0; off >>= 1) {
#pragma unroll
        for (int h = 0; h < 4; h++)
            lm[h] = fmaxf(lm[h], __shfl_xor_sync(0xffffffffu, lm[h], off));
    }
    if (lane == 0) {
#pragma unroll
        for (int h = 0; h < 4; h++) red_s[wid][h] = lm[h];
    }
    __syncthreads();
    if (tid < 4) {
        float m = red_s[0][tid];
#pragma unroll
        for (int w = 1; w < ATN_WARPS; w++) m = fmaxf(m, red_s[w][tid]);
        m_s[tid] = m;
    }
    __syncthreads();

    // ---- exp2 pass + row sums ----
    float lp[4] = {0.f, 0.f, 0.f, 0.f};
    const float m0 = m_s[0], m1 = m_s[1], m2 = m_s[2], m3 = m_s[3];
    for (int i = tid; i < len; i += ATN_THREADS) {
        float p0 = ex2f_fast(sc[i] - m0);           sc[i] = p0;            lp[0] += p0;
        float p1 = ex2f_fast(sc[SCP + i] - m1);     sc[SCP + i] = p1;      lp[1] += p1;
        float p2 = ex2f_fast(sc[2 * SCP + i] - m2); sc[2 * SCP + i] = p2;  lp[2] += p2;
        float p3 = ex2f_fast(sc[3 * SCP + i] - m3); sc[3 * SCP + i] = p3;  lp[3] += p3;
    }
    red4(lp[0], lp[1], lp[2], lp[3]);
    if (lane == 0) {
#pragma unroll
        for (int h = 0; h < 4; h++) red_s[wid][h] = lp[h];
    }
    __syncthreads();
    if (tid < 4) {
        float l = 0.f;
#pragma unroll
        for (int w = 0; w < ATN_WARPS; w++) l += red_s[w][tid];
        l_s[tid] = l;
    }
    __syncthreads();

    // ---- Phase B: weighted V accumulation (unroll 2, batched loads) ----
    const float* vbase = cache_v + (size_t)b * 8192 * 1024 + kvh * 128 + lane * 4;
    float4 o0 = {0,0,0,0}, o1 = {0,0,0,0}, o2 = {0,0,0,0}, o3 = {0,0,0,0};
    {
        int j = c0 + wid;
        for (; j + ATN_WARPS < jmax; j += 2 * ATN_WARPS) {
            float4 v0 = *(const float4*)(vbase + (size_t)j * 1024);
            float4 v1 = *(const float4*)(vbase + (size_t)(j + ATN_WARPS) * 1024);
            int jj = j - c0;
            float p0 = sc[jj], p1 = sc[SCP + jj], p2 = sc[2*SCP + jj], p3 = sc[3*SCP + jj];
            int jj2 = jj + ATN_WARPS;
            float q0 = sc[jj2], q1 = sc[SCP + jj2], q2 = sc[2*SCP + jj2], q3 = sc[3*SCP + jj2];
            o0.x += p0*v0.x + q0*v1.x; o0.y += p0*v0.y + q0*v1.y; o0.z += p0*v0.z + q0*v1.z; o0.w += p0*v0.w + q0*v1.w;
            o1.x += p1*v0.x + q1*v1.x; o1.y += p1*v0.y + q1*v1.y; o1.z += p1*v0.z + q1*v1.z; o1.w += p1*v0.w + q1*v1.w;
            o2.x += p2*v0.x + q2*v1.x; o2.y += p2*v0.y + q2*v1.y; o2.z += p2*v0.z + q2*v1.z; o2.w += p2*v0.w + q2*v1.w;
            o3.x += p3*v0.x + q3*v1.x; o3.y += p3*v0.y + q3*v1.y; o3.z += p3*v0.z + q3*v1.z; o3.w += p3*v0.w + q3*v1.w;
        }
        for (; j < jmax; j += ATN_WARPS) {
            float4 v0 = *(const float4*)(vbase + (size_t)j * 1024);
            int jj = j - c0;
            float p0 = sc[jj], p1 = sc[SCP + jj], p2 = sc[2*SCP + jj], p3 = sc[3*SCP + jj];
            o0.x += p0*v0.x; o0.y += p0*v0.y; o0.z += p0*v0.z; o0.w += p0*v0.w;
            o1.x += p1*v0.x; o1.y += p1*v0.y; o1.z += p1*v0.z; o1.w += p1*v0.w;
            o2.x += p2*v0.x; o2.y += p2*v0.y; o2.z += p2*v0.z; o2.w += p2*v0.w;
            o3.x += p3*v0.x; o3.y += p3*v0.y; o3.z += p3*v0.z; o3.w += p3*v0.w;
        }
        if (has_new && wid == 0) {
            int base = (5120 + kvh * 128 + lane * 4) * 16 + b;
            float4 vv;
            vv.x = g_qkv[base]; vv.y = g_qkv[base + 16]; vv.z = g_qkv[base + 32]; vv.w = g_qkv[base + 48];
            int jj = sp - c0;
            float p0 = sc[jj], p1 = sc[SCP + jj], p2 = sc[2*SCP + jj], p3 = sc[3*SCP + jj];
            o0.x += p0*vv.x; o0.y += p0*vv.y; o0.z += p0*vv.z; o0.w += p0*vv.w;
            o1.x += p1*vv.x; o1.y += p1*vv.y; o1.z += p1*vv.z; o1.w += p1*vv.w;
            o2.x += p2*vv.x; o2.y += p2*vv.y; o2.z += p2*vv.z; o2.w += p2*vv.w;
            o3.x += p3*vv.x; o3.y += p3*vv.y; o3.z += p3*vv.z; o3.w += p3*vv.w;
        }
    }

    // ---- cross-warp reduce + write partials ----
    *(float4*)&o_red[wid * 512 + 0 * 128 + lane * 4] = o0;
    *(float4*)&o_red[wid * 512 + 1 * 128 + lane * 4] = o1;
    *(float4*)&o_red[wid * 512 + 2 * 128 + lane * 4] = o2;
    *(float4*)&o_red[wid * 512 + 3 * 128 + lane * 4] = o3;
    __syncthreads();

    for (int e = tid; e < 512; e += ATN_THREADS) {
        float s = 0.f;
#pragma unroll
        for (int w = 0; w < ATN_WARPS; w++) s += o_red[w * 512 + e];
        int h = e >> 7, d = e & 127;
        g_part_o[(((b * 8 + kvh) * 4 + h) * SPLIT + chunk) * 128 + d] = s;
    }
    if (tid < 4) {
        int pidx = ((b * 8 + kvh) * 4 + tid) * SPLIT + chunk;
        g_part_ml[pidx * 2]     = m_s[tid];
        g_part_ml[pidx * 2 + 1] = l_s[tid];
    }
}

// ---------------- kernel 4: split-KV softmax combine -> attnT ----------------
__global__ void attn_combine_kernel() {
    const int qh = blockIdx.x & 31;
    const int b = blockIdx.x >> 5;
    const int kvh = qh >> 2, h = qh & 3;
    const int pidx = ((b * 8 + kvh) * 4 + h) * SPLIT;
    const int d = threadIdx.x;

    float mg[SPLIT], lg[SPLIT];
    float M = -1e30f;
#pragma unroll
    for (int g = 0; g < SPLIT; g++) {
        mg[g] = g_part_ml[(pidx + g) * 2];
        lg[g] = g_part_ml[(pidx + g) * 2 + 1];
        M = fmaxf(M, mg[g]);
    }
    float L = 0.f, wg[SPLIT];
#pragma unroll
    for (int g = 0; g < SPLIT; g++) {
        wg[g] = ex2f_fast(mg[g] - M);
        L += lg[g] * wg[g];
    }
    float s = 0.f;
#pragma unroll
    for (int g = 0; g < SPLIT; g++)
        s += g_part_o[(pidx + g) * 128 + d] * wg[g];

    g_attnT[(qh * 128 + d) * 16 + b] = s / L;
}

// ---------------- launch ----------------
extern "C" void kernel_launch(void* const* d_in, const int* in_sizes, int n_in,
                              void* d_out, int out_size) {
    const float* x  = (const float*)d_in[0];
    const int*   sp = (const int*)d_in[1];
    const float* fc = (const float*)d_in[2];
    const float* fs = (const float*)d_in[3];
    const float* ck = (const float*)d_in[4];
    const float* cv = (const float*)d_in[5];
    const float* wq = (const float*)d_in[6];
    const float* wk = (const float*)d_in[7];
    const float* wv = (const float*)d_in[8];
    const float* wo = (const float*)d_in[9];
    float* out = (float*)d_out;

    transpose_x_kernel<<<256, 256>>>(x);
    gemv16_kernel<<<384, 256>>>(wq, wk, wv, nullptr, fc, fs, 0);
    attn_partial_kernel<<<16 * 8 * SPLIT, ATN_THREADS>>>(ck, cv, sp);
    attn_combine_kernel<<<512, 128>>>();
    gemv16_kernel<<<256, 256>>>(wo, nullptr, nullptr, out, nullptr, nullptr, 1);
}

// round 3
// speedup vs baseline: 1.4210x; 1.0781x over previous
#include <cuda_runtime.h>
#include <math.h>

#define SPLIT 8
#define SCP 516          // score smem pitch (CH = ceil(4097/8) = 513)
#define ATN_THREADS 192  // 6 warps
#define ATN_WARPS 6

// ---------------- scratch (no allocations allowed) ----------------
__device__ float g_xT[4096 * 16];                     // x transposed [k][b]
__device__ float g_qkv[6144 * 16];                    // q(0..4095)/k(4096..5119)/v(5120..6143) rows x 16 batches
__device__ float g_attnT[4096 * 16];                  // attention out transposed [k][b]
__device__ float g_part_o[16 * 8 * 4 * SPLIT * 128];  // split-KV partial outputs
__device__ float g_part_ml[16 * 8 * 4 * SPLIT * 2];   // split-KV partial (m, l)

// ---------------- helpers ----------------
__device__ __forceinline__ unsigned long long ffma2(unsigned long long a, unsigned long long b, unsigned long long c) {
    unsigned long long d;
    asm("fma.rn.f32x2 %0, %1, %2, %3;" : "=l"(d) : "l"(a), "l"(b), "l"(c));
    return d;
}
__device__ __forceinline__ unsigned long long addf2(unsigned long long a, unsigned long long b) {
    unsigned long long d;
    asm("add.rn.f32x2 %0, %1, %2;" : "=l"(d) : "l"(a), "l"(b));
    return d;
}
__device__ __forceinline__ unsigned long long pack2(float v) {
    unsigned long long d;
    asm("mov.b64 %0, {%1, %1};" : "=l"(d) : "r"(__float_as_uint(v)));
    return d;
}
__device__ __forceinline__ float f2lo(unsigned long long u) { return __uint_as_float((unsigned)u); }
__device__ __forceinline__ float f2hi(unsigned long long u) { return __uint_as_float((unsigned)(u >> 32)); }
__device__ __forceinline__ float ex2f_fast(float x) {
    float y;
    asm("ex2.approx.ftz.f32 %0, %1;" : "=f"(y) : "f"(x));
    return y;
}

// Cheap 4-value warp reduction: 5 SHFL total (vs 20).
// Returns: lane l holds the full 32-lane sum of head (l & 3).
__device__ __forceinline__ float red4x(float s0, float s1, float s2, float s3, int lane) {
    const bool b1 = lane & 2;
    float t0 = b1 ? s2 : s0;
    float t1 = b1 ? s3 : s1;
    float u0 = b1 ? s0 : s2;
    float u1 = b1 ? s1 : s3;
    t0 += __shfl_xor_sync(0xffffffffu, u0, 2);
    t1 += __shfl_xor_sync(0xffffffffu, u1, 2);
    const bool b0 = lane & 1;
    float r = b0 ? t1 : t0;
    float w = b0 ? t0 : t1;
    r += __shfl_xor_sync(0xffffffffu, w, 1);
    r += __shfl_xor_sync(0xffffffffu, r, 4);
    r += __shfl_xor_sync(0xffffffffu, r, 8);
    r += __shfl_xor_sync(0xffffffffu, r, 16);
    return r;
}

// ---------------- kernel 1: tiled transpose x [16][4096] -> xT [4096][16] ----------------
__global__ void transpose_x_kernel(const float* __restrict__ x) {
    __shared__ float t[16][17];
    const int k0 = blockIdx.x * 16;
    t[threadIdx.y][threadIdx.x] = x[threadIdx.y * 4096 + k0 + threadIdx.x];
    __syncthreads();
    g_xT[(k0 + threadIdx.y) * 16 + threadIdx.x] = t[threadIdx.x][threadIdx.y];
}

// ---------------- kernel 2/5: 16-batch GEMV, 2 rows/warp, f32x2 packed FMA ----------------
__global__ __launch_bounds__(256) void gemv16_kernel(
    const float* __restrict__ Wa, const float* __restrict__ Wb, const float* __restrict__ Wc,
    float* __restrict__ outp,
    const float* __restrict__ fc, const float* __restrict__ fs, int mode)
{
    __shared__ __align__(16) float xs[512 * 20];
    const int tid = threadIdx.x, lane = tid & 31, wid = tid >> 5;
    const int r0 = blockIdx.x * 16 + wid * 2;

    const float* W;
    const float* xT;
    int row;
    if (mode == 0) {
        xT = g_xT;
        if (r0 < 4096)      { W = Wa; row = r0; }
        else if (r0 < 5120) { W = Wb; row = r0 - 4096; }
        else                { W = Wc; row = r0 - 5120; }
    } else {
        xT = g_attnT; W = Wa; row = r0;
    }
    float* op = (mode == 0) ? g_qkv : outp;

    unsigned long long acc[2][8];
#pragma unroll
    for (int r = 0; r < 2; r++)
#pragma unroll
        for (int p = 0; p < 8; p++) acc[r][p] = 0ull;

    const float4* xT4 = (const float4*)xT;
    for (int kb = 0; kb < 8; kb++) {
#pragma unroll
        for (int i = tid; i < 2048; i += 256) {
            int kl = i >> 2, q = i & 3;
            float4 v = xT4[(kb * 512 + kl) * 4 + q];
            *(float4*)&xs[kl * 20 + q * 4] = v;
        }
        __syncthreads();

        const float* wr = W + (size_t)row * 4096 + kb * 512;
#pragma unroll 8
        for (int it = 0; it < 16; it++) {
            int k = it * 32 + lane;
            unsigned long long p0 = pack2(wr[k]);
            unsigned long long p1 = pack2(wr[4096 + k]);
            const ulonglong2* xp = (const ulonglong2*)&xs[k * 20];
#pragma unroll
            for (int pp = 0; pp < 4; pp++) {
                ulonglong2 xv = xp[pp];
                acc[0][2 * pp]     = ffma2(p0, xv.x, acc[0][2 * pp]);
                acc[0][2 * pp + 1] = ffma2(p0, xv.y, acc[0][2 * pp + 1]);
                acc[1][2 * pp]     = ffma2(p1, xv.x, acc[1][2 * pp]);
                acc[1][2 * pp + 1] = ffma2(p1, xv.y, acc[1][2 * pp + 1]);
            }
        }
        __syncthreads();
    }

#pragma unroll
    for (int r = 0; r < 2; r++)
#pragma unroll
        for (int p = 0; p < 8; p++) {
#pragma unroll
            for (int off = 16; off > 0; off >>= 1) {
                unsigned long long o = __shfl_xor_sync(0xffffffffu, acc[r][p], off);
                acc[r][p] = addf2(acc[r][p], o);
            }
        }

    if (lane < 16) {
        const int b = lane;
        float v[2];
#pragma unroll
        for (int r = 0; r < 2; r++) {
            unsigned long long u = acc[r][b >> 1];
            v[r] = (b & 1) ? f2hi(u) : f2lo(u);
        }
        if (mode == 0) {
            if (r0 < 5120) {  // RoPE (r0 even -> adjacent rows form a rope pair)
                int i0 = (r0 & 127) >> 1;
                float c0 = fc[i0], s0 = fs[i0];
                float a0 = v[0] * c0 - v[1] * s0, b0 = v[0] * s0 + v[1] * c0;
                v[0] = a0; v[1] = b0;
                if (r0 < 4096) {  // fold softmax scale * log2(e) into q
                    const float SC = 1.4426950408889634f * 0.08838834764831843f;
                    v[0] *= SC; v[1] *= SC;
                }
            }
            op[r0 * 16 + b] = v[0];
            op[(r0 + 1) * 16 + b] = v[1];
        } else {
            op[b * 4096 + r0] = v[0];
            op[b * 4096 + r0 + 1] = v[1];
        }
    }
}

// ---------------- kernel 3: split-KV flash-decode partials ----------------
__global__ __launch_bounds__(ATN_THREADS, 7) void attn_partial_kernel(
    const float* __restrict__ cache_k, const float* __restrict__ cache_v,
    const int* __restrict__ sp_ptr)
{
    __shared__ __align__(16) float q_s[512];
    __shared__ __align__(16) float sc[4 * SCP];
    __shared__ __align__(16) float o_red[ATN_WARPS * 512];
    __shared__ float m_s[4], l_s[4];
    __shared__ float red_s[ATN_WARPS][4];

    const int tid = threadIdx.x, lane = tid & 31, wid = tid >> 5;
    const int blk = blockIdx.x;
    const int chunk = blk & (SPLIT - 1);
    const int kvh = (blk >> 3) & 7;
    const int b = blk >> 6;
    const int sp = *sp_ptr;
    const int kvlen = sp + 1;
    const int CH = (kvlen + SPLIT - 1) / SPLIT;
    const int c0 = chunk * CH;
    const int c1 = min(c0 + CH, kvlen);
    const int len = c1 - c0;
    const bool has_new = (sp >= c0 && sp < c1);
    const int jmax = min(c1, sp);   // cache-resident keys only

    for (int i = tid; i < 512; i += ATN_THREADS)
        q_s[i] = g_qkv[((kvh * 4 + (i >> 7)) * 128 + (i & 127)) * 16 + b];
    __syncthreads();

    float qr[4][4];
#pragma unroll
    for (int h = 0; h < 4; h++) {
        float4 t = *(const float4*)&q_s[h * 128 + lane * 4];
        qr[h][0] = t.x; qr[h][1] = t.y; qr[h][2] = t.z; qr[h][3] = t.w;
    }

    const float* kbase = cache_k + (size_t)b * 8192 * 1024 + kvh * 128 + lane * 4;

    // ---- Phase A: scores (unroll 2, cheap 5-SHFL reduction) ----
    {
        int j = c0 + wid;
        for (; j + ATN_WARPS < jmax; j += 2 * ATN_WARPS) {
            float4 k0 = *(const float4*)(kbase + (size_t)j * 1024);
            float4 k1 = *(const float4*)(kbase + (size_t)(j + ATN_WARPS) * 1024);
            float s0 = k0.x*qr[0][0] + k0.y*qr[0][1] + k0.z*qr[0][2] + k0.w*qr[0][3];
            float s1 = k0.x*qr[1][0] + k0.y*qr[1][1] + k0.z*qr[1][2] + k0.w*qr[1][3];
            float s2 = k0.x*qr[2][0] + k0.y*qr[2][1] + k0.z*qr[2][2] + k0.w*qr[2][3];
            float s3 = k0.x*qr[3][0] + k0.y*qr[3][1] + k0.z*qr[3][2] + k0.w*qr[3][3];
            float t0 = k1.x*qr[0][0] + k1.y*qr[0][1] + k1.z*qr[0][2] + k1.w*qr[0][3];
            float t1 = k1.x*qr[1][0] + k1.y*qr[1][1] + k1.z*qr[1][2] + k1.w*qr[1][3];
            float t2 = k1.x*qr[2][0] + k1.y*qr[2][1] + k1.z*qr[2][2] + k1.w*qr[2][3];
            float t3 = k1.x*qr[3][0] + k1.y*qr[3][1] + k1.z*qr[3][2] + k1.w*qr[3][3];
            float ra = red4x(s0, s1, s2, s3, lane);
            float rb = red4x(t0, t1, t2, t3, lane);
            if (lane < 4) {
                sc[lane * SCP + (j - c0)] = ra;
                sc[lane * SCP + (j - c0) + ATN_WARPS] = rb;
            }
        }
        for (; j < jmax; j += ATN_WARPS) {
            float4 k0 = *(const float4*)(kbase + (size_t)j * 1024);
            float s0 = k0.x*qr[0][0] + k0.y*qr[0][1] + k0.z*qr[0][2] + k0.w*qr[0][3];
            float s1 = k0.x*qr[1][0] + k0.y*qr[1][1] + k0.z*qr[1][2] + k0.w*qr[1][3];
            float s2 = k0.x*qr[2][0] + k0.y*qr[2][1] + k0.z*qr[2][2] + k0.w*qr[2][3];
            float s3 = k0.x*qr[3][0] + k0.y*qr[3][1] + k0.z*qr[3][2] + k0.w*qr[3][3];
            float ra = red4x(s0, s1, s2, s3, lane);
            if (lane < 4) sc[lane * SCP + (j - c0)] = ra;
        }
        if (has_new && wid == 0) {
            int base = (4096 + kvh * 128 + lane * 4) * 16 + b;
            float4 kv;
            kv.x = g_qkv[base]; kv.y = g_qkv[base + 16]; kv.z = g_qkv[base + 32]; kv.w = g_qkv[base + 48];
            float s0 = kv.x*qr[0][0] + kv.y*qr[0][1] + kv.z*qr[0][2] + kv.w*qr[0][3];
            float s1 = kv.x*qr[1][0] + kv.y*qr[1][1] + kv.z*qr[1][2] + kv.w*qr[1][3];
            float s2 = kv.x*qr[2][0] + kv.y*qr[2][1] + kv.z*qr[2][2] + kv.w*qr[2][3];
            float s3 = kv.x*qr[3][0] + kv.y*qr[3][1] + kv.z*qr[3][2] + kv.w*qr[3][3];
            float ra = red4x(s0, s1, s2, s3, lane);
            if (lane < 4) sc[lane * SCP + (sp - c0)] = ra;
        }
    }
    __syncthreads();

    // ---- chunk max per head ----
    float lm[4] = {-1e30f, -1e30f, -1e30f, -1e30f};
    for (int i = tid; i < len; i += ATN_THREADS) {
#pragma unroll
        for (int h = 0; h < 4; h++) lm[h] = fmaxf(lm[h], sc[h * SCP + i]);
    }
#pragma unroll
    for (int off = 16; off > 0; off >>= 1) {
#pragma unroll
        for (int h = 0; h < 4; h++)
            lm[h] = fmaxf(lm[h], __shfl_xor_sync(0xffffffffu, lm[h], off));
    }
    if (lane == 0) {
#pragma unroll
        for (int h = 0; h < 4; h++) red_s[wid][h] = lm[h];
    }
    __syncthreads();
    if (tid < 4) {
        float m = red_s[0][tid];
#pragma unroll
        for (int w = 1; w < ATN_WARPS; w++) m = fmaxf(m, red_s[w][tid]);
        m_s[tid] = m;
    }
    __syncthreads();

    // ---- exp2 pass + row sums ----
    float lp0 = 0.f, lp1 = 0.f, lp2 = 0.f, lp3 = 0.f;
    const float m0 = m_s[0], m1 = m_s[1], m2 = m_s[2], m3 = m_s[3];
    for (int i = tid; i < len; i += ATN_THREADS) {
        float p0 = ex2f_fast(sc[i] - m0);           sc[i] = p0;            lp0 += p0;
        float p1 = ex2f_fast(sc[SCP + i] - m1);     sc[SCP + i] = p1;      lp1 += p1;
        float p2 = ex2f_fast(sc[2 * SCP + i] - m2); sc[2 * SCP + i] = p2;  lp2 += p2;
        float p3 = ex2f_fast(sc[3 * SCP + i] - m3); sc[3 * SCP + i] = p3;  lp3 += p3;
    }
    {
        float r = red4x(lp0, lp1, lp2, lp3, lane);
        if (lane < 4) red_s[wid][lane] = r;
    }
    __syncthreads();
    if (tid < 4) {
        float l = 0.f;
#pragma unroll
        for (int w = 0; w < ATN_WARPS; w++) l += red_s[w][tid];
        l_s[tid] = l;
    }
    __syncthreads();

    // ---- Phase B: weighted V accumulation (unroll 2) ----
    const float* vbase = cache_v + (size_t)b * 8192 * 1024 + kvh * 128 + lane * 4;
    float4 o0 = {0,0,0,0}, o1 = {0,0,0,0}, o2 = {0,0,0,0}, o3 = {0,0,0,0};
    {
        int j = c0 + wid;
        for (; j + ATN_WARPS < jmax; j += 2 * ATN_WARPS) {
            float4 v0 = *(const float4*)(vbase + (size_t)j * 1024);
            float4 v1 = *(const float4*)(vbase + (size_t)(j + ATN_WARPS) * 1024);
            int jj = j - c0;
            float p0 = sc[jj], p1 = sc[SCP + jj], p2 = sc[2*SCP + jj], p3 = sc[3*SCP + jj];
            int jj2 = jj + ATN_WARPS;
            float q0 = sc[jj2], q1 = sc[SCP + jj2], q2 = sc[2*SCP + jj2], q3 = sc[3*SCP + jj2];
            o0.x += p0*v0.x + q0*v1.x; o0.y += p0*v0.y + q0*v1.y; o0.z += p0*v0.z + q0*v1.z; o0.w += p0*v0.w + q0*v1.w;
            o1.x += p1*v0.x + q1*v1.x; o1.y += p1*v0.y + q1*v1.y; o1.z += p1*v0.z + q1*v1.z; o1.w += p1*v0.w + q1*v1.w;
            o2.x += p2*v0.x + q2*v1.x; o2.y += p2*v0.y + q2*v1.y; o2.z += p2*v0.z + q2*v1.z; o2.w += p2*v0.w + q2*v1.w;
            o3.x += p3*v0.x + q3*v1.x; o3.y += p3*v0.y + q3*v1.y; o3.z += p3*v0.z + q3*v1.z; o3.w += p3*v0.w + q3*v1.w;
        }
        for (; j < jmax; j += ATN_WARPS) {
            float4 v0 = *(const float4*)(vbase + (size_t)j * 1024);
            int jj = j - c0;
            float p0 = sc[jj], p1 = sc[SCP + jj], p2 = sc[2*SCP + jj], p3 = sc[3*SCP + jj];
            o0.x += p0*v0.x; o0.y += p0*v0.y; o0.z += p0*v0.z; o0.w += p0*v0.w;
            o1.x += p1*v0.x; o1.y += p1*v0.y; o1.z += p1*v0.z; o1.w += p1*v0.w;
            o2.x += p2*v0.x; o2.y += p2*v0.y; o2.z += p2*v0.z; o2.w += p2*v0.w;
            o3.x += p3*v0.x; o3.y += p3*v0.y; o3.z += p3*v0.z; o3.w += p3*v0.w;
        }
        if (has_new && wid == 0) {
            int base = (5120 + kvh * 128 + lane * 4) * 16 + b;
            float4 vv;
            vv.x = g_qkv[base]; vv.y = g_qkv[base + 16]; vv.z = g_qkv[base + 32]; vv.w = g_qkv[base + 48];
            int jj = sp - c0;
            float p0 = sc[jj], p1 = sc[SCP + jj], p2 = sc[2*SCP + jj], p3 = sc[3*SCP + jj];
            o0.x += p0*vv.x; o0.y += p0*vv.y; o0.z += p0*vv.z; o0.w += p0*vv.w;
            o1.x += p1*vv.x; o1.y += p1*vv.y; o1.z += p1*vv.z; o1.w += p1*vv.w;
            o2.x += p2*vv.x; o2.y += p2*vv.y; o2.z += p2*vv.z; o2.w += p2*vv.w;
            o3.x += p3*vv.x; o3.y += p3*vv.y; o3.z += p3*vv.z; o3.w += p3*vv.w;
        }
    }

    // ---- cross-warp reduce + write partials ----
    *(float4*)&o_red[wid * 512 + 0 * 128 + lane * 4] = o0;
    *(float4*)&o_red[wid * 512 + 1 * 128 + lane * 4] = o1;
    *(float4*)&o_red[wid * 512 + 2 * 128 + lane * 4] = o2;
    *(float4*)&o_red[wid * 512 + 3 * 128 + lane * 4] = o3;
    __syncthreads();

    for (int e = tid; e < 512; e += ATN_THREADS) {
        float s = 0.f;
#pragma unroll
        for (int w = 0; w < ATN_WARPS; w++) s += o_red[w * 512 + e];
        int h = e >> 7, d = e & 127;
        g_part_o[(((b * 8 + kvh) * 4 + h) * SPLIT + chunk) * 128 + d] = s;
    }
    if (tid < 4) {
        int pidx = ((b * 8 + kvh) * 4 + tid) * SPLIT + chunk;
        g_part_ml[pidx * 2]     = m_s[tid];
        g_part_ml[pidx * 2 + 1] = l_s[tid];
    }
}

// ---------------- kernel 4: split-KV softmax combine -> attnT ----------------
__global__ void attn_combine_kernel() {
    const int qh = blockIdx.x & 31;
    const int b = blockIdx.x >> 5;
    const int kvh = qh >> 2, h = qh & 3;
    const int pidx = ((b * 8 + kvh) * 4 + h) * SPLIT;
    const int d = threadIdx.x;

    float mg[SPLIT], lg[SPLIT];
    float M = -1e30f;
#pragma unroll
    for (int g = 0; g < SPLIT; g++) {
        mg[g] = g_part_ml[(pidx + g) * 2];
        lg[g] = g_part_ml[(pidx + g) * 2 + 1];
        M = fmaxf(M, mg[g]);
    }
    float L = 0.f, wg[SPLIT];
#pragma unroll
    for (int g = 0; g < SPLIT; g++) {
        wg[g] = ex2f_fast(mg[g] - M);
        L += lg[g] * wg[g];
    }
    float s = 0.f;
#pragma unroll
    for (int g = 0; g < SPLIT; g++)
        s += g_part_o[(pidx + g) * 128 + d] * wg[g];

    g_attnT[(qh * 128 + d) * 16 + b] = s / L;
}

// ---------------- launch ----------------
extern "C" void kernel_launch(void* const* d_in, const int* in_sizes, int n_in,
                              void* d_out, int out_size) {
    const float* x  = (const float*)d_in[0];
    const int*   sp = (const int*)d_in[1];
    const float* fc = (const float*)d_in[2];
    const float* fs = (const float*)d_in[3];
    const float* ck = (const float*)d_in[4];
    const float* cv = (const float*)d_in[5];
    const float* wq = (const float*)d_in[6];
    const float* wk = (const float*)d_in[7];
    const float* wv = (const float*)d_in[8];
    const float* wo = (const float*)d_in[9];
    float* out = (float*)d_out;

    transpose_x_kernel<<<256, dim3(16, 16)>>>(x);
    gemv16_kernel<<<384, 256>>>(wq, wk, wv, nullptr, fc, fs, 0);
    attn_partial_kernel<<<16 * 8 * SPLIT, ATN_THREADS>>>(ck, cv, sp);
    attn_combine_kernel<<<512, 128>>>();
    gemv16_kernel<<<256, 256>>>(wo, nullptr, nullptr, out, nullptr, nullptr, 1);
}